// round 13
// baseline (speedup 1.0000x reference)
#include <cuda_runtime.h>
#include <cuda_bf16.h>
#include <math.h>
#include <stdint.h>

// ---------------------------------------------------------------- dims
#define NB   8
#define NT   2048
#define NC   768
#define NE   8
#define NKT  2
#define NH   3072
#define NCAP 640
#define NM   (NB * NCAP)   // 5120 rows per expert
#define WSZ  ((size_t)NE * NC * NH)   // elements per weight tensor

// ---------------------------------------------------------------- helpers
__device__ __forceinline__ uint32_t smem_u32(const void* p) {
    uint32_t a;
    asm("{ .reg .u64 t; cvta.to.shared.u64 t, %1; cvt.u32.u64 %0, t; }"
        : "=r"(a) : "l"(p));
    return a;
}
__device__ __forceinline__ void ldsm4(uint32_t* r, uint32_t a) {
    asm volatile("ldmatrix.sync.aligned.m8n8.x4.shared.b16 {%0,%1,%2,%3}, [%4];"
        : "=r"(r[0]), "=r"(r[1]), "=r"(r[2]), "=r"(r[3]) : "r"(a));
}
__device__ __forceinline__ void ldsm4t(uint32_t* r, uint32_t a) {
    asm volatile("ldmatrix.sync.aligned.m8n8.x4.trans.shared.b16 {%0,%1,%2,%3}, [%4];"
        : "=r"(r[0]), "=r"(r[1]), "=r"(r[2]), "=r"(r[3]) : "r"(a));
}
__device__ __forceinline__ void mma_bf16(float* d, const uint32_t* a, const uint32_t* b) {
    asm volatile(
        "mma.sync.aligned.m16n8k16.row.col.f32.bf16.bf16.f32 "
        "{%0,%1,%2,%3}, {%4,%5,%6,%7}, {%8,%9}, {%0,%1,%2,%3};"
        : "+f"(d[0]), "+f"(d[1]), "+f"(d[2]), "+f"(d[3])
        : "r"(a[0]), "r"(a[1]), "r"(a[2]), "r"(a[3]), "r"(b[0]), "r"(b[1]));
}
// split float4 into packed bf16 hi (uint2) and lo residual (uint2)
__device__ __forceinline__ void split4(float4 v, uint2& h, uint2& l) {
    __nv_bfloat16 h0 = __float2bfloat16(v.x), h1 = __float2bfloat16(v.y);
    __nv_bfloat16 h2 = __float2bfloat16(v.z), h3 = __float2bfloat16(v.w);
    float r0 = v.x - __bfloat162float(h0), r1 = v.y - __bfloat162float(h1);
    float r2 = v.z - __bfloat162float(h2), r3 = v.w - __bfloat162float(h3);
    h.x = (uint32_t)__bfloat16_as_ushort(h0) | ((uint32_t)__bfloat16_as_ushort(h1) << 16);
    h.y = (uint32_t)__bfloat16_as_ushort(h2) | ((uint32_t)__bfloat16_as_ushort(h3) << 16);
    l.x = (uint32_t)__bfloat16_as_ushort(__float2bfloat16(r0))
        | ((uint32_t)__bfloat16_as_ushort(__float2bfloat16(r1)) << 16);
    l.y = (uint32_t)__bfloat16_as_ushort(__float2bfloat16(r2))
        | ((uint32_t)__bfloat16_as_ushort(__float2bfloat16(r3)) << 16);
}
// split float2 -> packed bf16 hi + lo residual (in-register A fragment build)
__device__ __forceinline__ void cvt2(float2 v, uint32_t& h, uint32_t& l) {
    __nv_bfloat16 h0 = __float2bfloat16(v.x), h1 = __float2bfloat16(v.y);
    float r0 = v.x - __bfloat162float(h0);
    float r1 = v.y - __bfloat162float(h1);
    h = (uint32_t)__bfloat16_as_ushort(h0) | ((uint32_t)__bfloat16_as_ushort(h1) << 16);
    l = (uint32_t)__bfloat16_as_ushort(__float2bfloat16(r0))
      | ((uint32_t)__bfloat16_as_ushort(__float2bfloat16(r1)) << 16);
}
#define CPA16(dst, src) \
    asm volatile("cp.async.cg.shared.global [%0], [%1], 16;" \
                 :: "r"((uint32_t)(dst)), "l"(src) : "memory")
#define CP_COMMIT()  asm volatile("cp.async.commit_group;" ::: "memory")
#define CP_WAIT0()   asm volatile("cp.async.wait_group 0;"  ::: "memory")

// ---------------------------------------------------------------- scratch (≈654MB total)
__device__ __nv_bfloat16 g_acth[(size_t)NE * NM * NH];  // activation hi (252MB)
__device__ __nv_bfloat16 g_actl[(size_t)NE * NM * NH];  // activation lo (252MB)
// union buffer (151MB): phase 1 = fc/gate weight splits, phase 2 = g_o.
__device__ __align__(1024) unsigned char g_u[4 * WSZ * 2];
__device__ float g_p  [NB * NT * NKT];
__device__ int   g_ei [NB * NT * NKT];
__device__ int   g_pos[NB * NT * NKT];
__device__ int   g_src[NE * NM];

// ---------------------------------------------------------------- prep: split BOTH mlp1 weights
__global__ void wsplit2_kernel(const float* __restrict__ wfc,
                               const float* __restrict__ wgt) {
    __nv_bfloat16* gu = (__nv_bfloat16*)g_u;
    size_t half = WSZ / 4;                          // float4 count per tensor
    size_t i = (size_t)blockIdx.x * 256 + threadIdx.x;
    const float* src; __nv_bfloat16 *oh, *ol; size_t j;
    if (i < half) { src = wfc; oh = gu + 0 * WSZ; ol = gu + 1 * WSZ; j = i; }
    else          { src = wgt; oh = gu + 2 * WSZ; ol = gu + 3 * WSZ; j = i - half; }
    float4 v = ((const float4*)src)[j];
    uint2 h, l;
    split4(v, h, l);
    ((uint2*)oh)[j] = h;
    ((uint2*)ol)[j] = l;
}

// ---------------------------------------------------------------- router (unchanged, passing)
__global__ void router_kernel(const float* __restrict__ x,
                              const float* __restrict__ wr,
                              const float* __restrict__ br) {
    __shared__ float ws[NC * NE];
    int tid = threadIdx.x;
    const float4* wr4 = (const float4*)wr;
    float4* ws4 = (float4*)ws;
    #pragma unroll
    for (int i = tid; i < NC * NE / 4; i += 256) ws4[i] = wr4[i];
    __syncthreads();

    int warp = tid >> 5, lane = tid & 31;
    int token = blockIdx.x * 8 + warp;
    const float* xrow = x + (size_t)token * NC;

    float acc[NE];
    #pragma unroll
    for (int e = 0; e < NE; e++) acc[e] = 0.f;
    for (int c = lane; c < NC; c += 32) {
        float xv = xrow[c];
        #pragma unroll
        for (int e = 0; e < NE; e++) acc[e] = fmaf(xv, ws[c * NE + e], acc[e]);
    }
    #pragma unroll
    for (int e = 0; e < NE; e++) {
        #pragma unroll
        for (int off = 16; off; off >>= 1)
            acc[e] += __shfl_xor_sync(0xffffffffu, acc[e], off);
    }
    if (lane == 0) {
        float l[NE], p[NE];
        float mx = -1e30f;
        #pragma unroll
        for (int e = 0; e < NE; e++) { l[e] = acc[e] + br[e]; mx = fmaxf(mx, l[e]); }
        float s = 0.f;
        #pragma unroll
        for (int e = 0; e < NE; e++) { p[e] = expf(l[e] - mx); s += p[e]; }
        float inv = 1.f / s;
        #pragma unroll
        for (int e = 0; e < NE; e++) p[e] *= inv;

        int i1 = 0; float p1 = p[0];
        #pragma unroll
        for (int e = 1; e < NE; e++) if (p[e] > p1) { p1 = p[e]; i1 = e; }
        int i2 = -1; float p2 = -1.f;
        #pragma unroll
        for (int e = 0; e < NE; e++) if (e != i1 && p[e] > p2) { p2 = p[e]; i2 = e; }

        g_p [token * 2 + 0] = p1;  g_p [token * 2 + 1] = p2;
        g_ei[token * 2 + 0] = i1;  g_ei[token * 2 + 1] = i2;
    }
}

// capacity scan (absorbs fill_src; exact k-major cumsum order per batch)
__global__ void pos_kernel() {
    __shared__ int cnt[8][NE];
    for (int i = threadIdx.x; i < NE * NM; i += 256) g_src[i] = -1;
    int w = threadIdx.x >> 5, lane = threadIdx.x & 31;
    int b = w;
    if (lane < NE) cnt[w][lane] = 0;
    __syncthreads();
    for (int k = 0; k < NKT; k++) {
        for (int t0 = 0; t0 < NT; t0 += 32) {
            int t = t0 + lane;
            int e = g_ei[(b * NT + t) * NKT + k];
            unsigned mask = __match_any_sync(0xffffffffu, e);
            int prefix = __popc(mask & ((1u << lane) - 1u));
            int base = cnt[w][e];
            __syncwarp();
            int pos = base + prefix;
            g_pos[(b * NT + t) * NKT + k] = pos;
            if (pos < NCAP) g_src[e * NM + b * NCAP + pos] = b * NT + t;
            if (lane == (31 - __clz(mask))) cnt[w][e] = base + __popc(mask);
            __syncwarp();
        }
    }
}

// ---------------------------------------------------------------- mlp1 (HMMA hi/lo; A direct-to-reg, B cp.async)
// smem per stage: 4 B matrices x [16 rows x 144B] = 9216 B; 2 stages.
#define BSTG1 9216
#define M1_FH 0
#define M1_FL 2304
#define M1_GH 4608
#define M1_GL 6912

__global__ void __launch_bounds__(256, 2) mlp1_kernel(const float* __restrict__ x,
                                                      const float* __restrict__ bfc,
                                                      const float* __restrict__ bgt) {
    __shared__ __align__(16) unsigned char SM[2 * BSTG1];   // 18432 B
    __shared__ int s_src[128];
    const uint32_t sb = smem_u32(SM);
    const int tid = threadIdx.x;
    const int e = blockIdx.z;
    const int m0 = blockIdx.x * 128, n0 = blockIdx.y * 64;   // m fastest (weights dedup in L2)

    if (tid < 128) s_src[tid] = g_src[e * NM + m0 + tid];

    const __nv_bfloat16* Wfh = (const __nv_bfloat16*)g_u + 0 * WSZ + (size_t)e * NC * NH;
    const __nv_bfloat16* Wfl = (const __nv_bfloat16*)g_u + 1 * WSZ + (size_t)e * NC * NH;
    const __nv_bfloat16* Wgh = (const __nv_bfloat16*)g_u + 2 * WSZ + (size_t)e * NC * NH;
    const __nv_bfloat16* Wgl = (const __nv_bfloat16*)g_u + 3 * WSZ + (size_t)e * NC * NH;

    const int wid = tid >> 5, lane = tid & 31;
    const int mwarp = wid >> 1, nwarp = wid & 1;
    const uint32_t bt_off = (uint32_t)(lane & 15) * 144 + ((lane & 16) ? 16 : 0) + nwarp * 64;
    const int kq = (lane & 3) * 2;   // k-pair offset within fragment

    float acch[2][4][4] = {};
    float accg[2][4][4] = {};

    // cp.async for the 4 pre-split weight matrices: 512 x 16B chunks, 2/thread
    auto cpB = [&](int s, int buf) {
        const int k0 = s * 16;
        const uint32_t base = sb + buf * BSTG1;
        #pragma unroll
        for (int i = 0; i < 2; i++) {
            int j = tid + i * 256;
            int mat = j >> 7;             // 0..3
            int jj = j & 127;
            int r = jj >> 3, ch = jj & 7; // k-row, 16B chunk
            const __nv_bfloat16* w = (mat < 2) ? (mat == 0 ? Wfh : Wfl)
                                               : (mat == 2 ? Wgh : Wgl);
            uint32_t off = (mat < 2) ? (mat == 0 ? M1_FH : M1_FL)
                                     : (mat == 2 ? M1_GH : M1_GL);
            CPA16(base + off + (uint32_t)r * 144 + ch * 16,
                  w + (size_t)(k0 + r) * NH + n0 + ch * 8);
        }
    };

    cpB(0, 0);
    CP_COMMIT();
    __syncthreads();   // s_src visible

    // per-lane A row pointers (rows: mwarp*32 + mt*16 + {0,8} + lane/4)
    const float* rp[4];
    {
        const int lr = mwarp * 32 + (lane >> 2);
        #pragma unroll
        for (int i = 0; i < 4; i++) {
            int s_ = s_src[lr + i * 8];
            rp[i] = (s_ >= 0) ? (x + (size_t)s_ * NC) : (const float*)0;
        }
    }

    const int NS = NC / 16;   // 48
    for (int s = 0; s < NS; s++) {
        const int buf = s & 1;
        CP_WAIT0();
        __syncthreads();                 // buf filled; buf^1 free (all warps done s-1)
        if (s + 1 < NS) {
            cpB(s + 1, buf ^ 1);
            CP_COMMIT();
        }
        const uint32_t base = sb + buf * BSTG1;
        const int k0 = s * 16;

        // A fragments: direct LDG + in-register hi/lo split (bitwise same values as before)
        uint32_t ah[2][4], al[2][4];
        #pragma unroll
        for (int mt = 0; mt < 2; mt++) {
            #pragma unroll
            for (int hf = 0; hf < 2; hf++) {
                const float* p = rp[mt * 2 + hf];
                float2 v0 = p ? *(const float2*)(p + k0 + kq)
                              : make_float2(0.f, 0.f);
                float2 v1 = p ? *(const float2*)(p + k0 + kq + 8)
                              : make_float2(0.f, 0.f);
                cvt2(v0, ah[mt][hf],     al[mt][hf]);
                cvt2(v1, ah[mt][2 + hf], al[mt][2 + hf]);
            }
        }

        uint32_t fh[2][4], fl[2][4], gh[2][4], gl[2][4];
        #pragma unroll
        for (int q = 0; q < 2; q++) {
            uint32_t bo = bt_off + q * 32;
            ldsm4t(fh[q], base + M1_FH + bo);
            ldsm4t(fl[q], base + M1_FL + bo);
            ldsm4t(gh[q], base + M1_GH + bo);
            ldsm4t(gl[q], base + M1_GL + bo);
        }
        #pragma unroll
        for (int mt = 0; mt < 2; mt++)
            #pragma unroll
            for (int nt = 0; nt < 4; nt++) {
                const uint32_t* FH = &fh[nt >> 1][(nt & 1) * 2];
                const uint32_t* FL = &fl[nt >> 1][(nt & 1) * 2];
                const uint32_t* GH = &gh[nt >> 1][(nt & 1) * 2];
                const uint32_t* GL = &gl[nt >> 1][(nt & 1) * 2];
                mma_bf16(acch[mt][nt], ah[mt], FH);
                mma_bf16(acch[mt][nt], al[mt], FH);
                mma_bf16(acch[mt][nt], ah[mt], FL);
                mma_bf16(accg[mt][nt], ah[mt], GH);
                mma_bf16(accg[mt][nt], al[mt], GH);
                mma_bf16(accg[mt][nt], ah[mt], GL);
            }
    }

    // epilogue: silu(h*g) -> bf16 hi/lo activations
    const int qr = lane >> 2, qc = (lane & 3) * 2;
    #pragma unroll
    for (int mt = 0; mt < 2; mt++) {
        #pragma unroll
        for (int nt = 0; nt < 4; nt++) {
            const int col = n0 + nwarp * 32 + nt * 8 + qc;
            const float b0 = bfc[e * NH + col], b1 = bfc[e * NH + col + 1];
            const float c0 = bgt[e * NH + col], c1 = bgt[e * NH + col + 1];
            #pragma unroll
            for (int hf = 0; hf < 2; hf++) {
                const int row = m0 + mwarp * 32 + mt * 16 + qr + hf * 8;
                float h0 = acch[mt][nt][hf * 2 + 0] + b0;
                float h1 = acch[mt][nt][hf * 2 + 1] + b1;
                float g0 = accg[mt][nt][hf * 2 + 0] + c0;
                float g1 = accg[mt][nt][hf * 2 + 1] + c1;
                float z0 = h0 * g0, z1 = h1 * g1;
                float v0 = z0 / (1.f + expf(-z0));
                float v1 = z1 / (1.f + expf(-z1));
                __nv_bfloat16 H0 = __float2bfloat16(v0), H1 = __float2bfloat16(v1);
                float r0 = v0 - __bfloat162float(H0);
                float r1 = v1 - __bfloat162float(H1);
                uint32_t hi = (uint32_t)__bfloat16_as_ushort(H0)
                            | ((uint32_t)__bfloat16_as_ushort(H1) << 16);
                uint32_t lo = (uint32_t)__bfloat16_as_ushort(__float2bfloat16(r0))
                            | ((uint32_t)__bfloat16_as_ushort(__float2bfloat16(r1)) << 16);
                size_t off = ((size_t)(e * NM + row)) * NH + col;
                *(uint32_t*)(g_acth + off) = hi;
                *(uint32_t*)(g_actl + off) = lo;
            }
        }
    }
}

// ---------------------------------------------------------------- mlp2 (HMMA hi/lo, CTA 128x128, reg-prefetch) — unchanged from R12
#define STG2  20992
#define M2_AH 0
#define M2_AL 6144
#define M2_BH 12288
#define M2_BL 16640

__global__ void __launch_bounds__(256) mlp2_kernel(const float* __restrict__ wp,
                                                   const float* __restrict__ bp) {
    __shared__ __align__(16) unsigned char SM[2 * STG2];   // 41984 B
    const uint32_t sb = smem_u32(SM);
    const int tid = threadIdx.x;
    const int e = blockIdx.z;
    const int n0 = blockIdx.x * 128, m0 = blockIdx.y * 128;

    const __nv_bfloat16* Ah = g_acth + ((size_t)e * NM + m0) * NH;
    const __nv_bfloat16* Al = g_actl + ((size_t)e * NM + m0) * NH;
    const float* W = wp + (size_t)e * NH * NC;   // [K=3072][N=768]
    float* g_o = (float*)g_u;                    // reuse union buffer

    const int wid = tid >> 5, lane = tid & 31;
    const int mwarp = wid >> 1, nwarp = wid & 1;   // warp tile 32 x 64
    const uint32_t a_off = (uint32_t)(mwarp * 32 + (lane & 15)) * 48 + ((lane & 16) ? 16 : 0);
    const uint32_t bt_off = (uint32_t)(lane & 15) * 272 + ((lane & 16) ? 16 : 0) + nwarp * 128;

    float acc[2][8][4] = {};

    uint2 pAh[2], pAl[2];
    float4 pB[2];

    auto ld_stage = [&](int s) {
        const int k0 = s * 16;
        #pragma unroll
        for (int i = 0; i < 2; i++) {
            int j = tid + i * 256;
            int r = j >> 2, ch = j & 3;
            size_t goff = (size_t)r * NH + k0 + ch * 4;
            pAh[i] = *(const uint2*)(Ah + goff);
            pAl[i] = *(const uint2*)(Al + goff);
        }
        #pragma unroll
        for (int i = 0; i < 2; i++) {
            int j = tid + i * 256;
            int r = j >> 5, ch = j & 31;   // 16 k-rows x 32 float4 chunks
            pB[i] = *(const float4*)(W + (size_t)(k0 + r) * NC + n0 + ch * 4);
        }
    };
    auto st_stage = [&](int buf) {
        const uint32_t base = buf * STG2;
        #pragma unroll
        for (int i = 0; i < 2; i++) {
            int j = tid + i * 256;
            int r = j >> 2, ch = j & 3;
            uint32_t d = base + (uint32_t)r * 48 + ch * 8;
            *(uint2*)(SM + M2_AH + d) = pAh[i];
            *(uint2*)(SM + M2_AL + d) = pAl[i];
        }
        #pragma unroll
        for (int i = 0; i < 2; i++) {
            int j = tid + i * 256;
            int r = j >> 5, ch = j & 31;
            uint2 h, l;
            split4(pB[i], h, l);
            uint32_t d = base + (uint32_t)r * 272 + ch * 8;
            *(uint2*)(SM + M2_BH + d) = h;
            *(uint2*)(SM + M2_BL + d) = l;
        }
    };

    const int NS = NH / 16;   // 192
    ld_stage(0);
    for (int s = 0; s < NS; s++) {
        const int buf = s & 1;
        st_stage(buf);
        __syncthreads();
        if (s + 1 < NS) ld_stage(s + 1);
        const uint32_t base = sb + buf * STG2;

        uint32_t ah[2][4], al[2][4];
        #pragma unroll
        for (int mt = 0; mt < 2; mt++) {
            ldsm4(ah[mt], base + M2_AH + a_off + mt * 768);
            ldsm4(al[mt], base + M2_AL + a_off + mt * 768);
        }
        uint32_t bh[4][4], bl[4][4];
        #pragma unroll
        for (int q = 0; q < 4; q++) {
            uint32_t bo = bt_off + q * 32;
            ldsm4t(bh[q], base + M2_BH + bo);
            ldsm4t(bl[q], base + M2_BL + bo);
        }
        #pragma unroll
        for (int mt = 0; mt < 2; mt++)
            #pragma unroll
            for (int nt = 0; nt < 8; nt++) {
                const uint32_t* BH = &bh[nt >> 1][(nt & 1) * 2];
                const uint32_t* BL = &bl[nt >> 1][(nt & 1) * 2];
                mma_bf16(acc[mt][nt], ah[mt], BH);
                mma_bf16(acc[mt][nt], al[mt], BH);
                mma_bf16(acc[mt][nt], ah[mt], BL);
            }
    }

    const int qr = lane >> 2, qc = (lane & 3) * 2;
    #pragma unroll
    for (int mt = 0; mt < 2; mt++) {
        #pragma unroll
        for (int nt = 0; nt < 8; nt++) {
            const int col = n0 + nwarp * 64 + nt * 8 + qc;
            const float b0 = bp[e * NC + col], b1 = bp[e * NC + col + 1];
            #pragma unroll
            for (int hf = 0; hf < 2; hf++) {
                const int row = m0 + mwarp * 32 + mt * 16 + qr + hf * 8;
                float2 o;
                o.x = acc[mt][nt][hf * 2 + 0] + b0;
                o.y = acc[mt][nt][hf * 2 + 1] + b1;
                *(float2*)(g_o + ((size_t)(e * NM + row)) * NC + col) = o;
            }
        }
    }
}

// ---------------------------------------------------------------- combine (reads g_o from union)
__global__ void combine_kernel(float* __restrict__ out) {
    const float* g_o = (const float*)g_u;
    int token = blockIdx.x;
    int b = token / NT;

    int e0 = g_ei[token * 2 + 0], e1 = g_ei[token * 2 + 1];
    float p0 = g_p[token * 2 + 0], p1 = g_p[token * 2 + 1];
    int q0 = min(g_pos[token * 2 + 0], NCAP - 1);
    int q1 = min(g_pos[token * 2 + 1], NCAP - 1);

    const float4* r0 = (const float4*)(g_o + ((size_t)e0 * NM + b * NCAP + q0) * NC);
    const float4* r1 = (const float4*)(g_o + ((size_t)e1 * NM + b * NCAP + q1) * NC);

    int c = threadIdx.x;
    float4 v0 = r0[c], v1 = r1[c];
    float4 o;
    o.x = p0 * v0.x + p1 * v1.x;
    o.y = p0 * v0.y + p1 * v1.y;
    o.z = p0 * v0.z + p1 * v1.z;
    o.w = p0 * v0.w + p1 * v1.w;
    ((float4*)out)[(size_t)token * (NC / 4) + c] = o;
}

// ---------------------------------------------------------------- launch
extern "C" void kernel_launch(void* const* d_in, const int* in_sizes, int n_in,
                              void* d_out, int out_size) {
    const float* x        = (const float*)d_in[0];
    const float* w_router = (const float*)d_in[1];
    const float* b_router = (const float*)d_in[2];
    const float* w_c_fc   = (const float*)d_in[3];
    const float* b_c_fc   = (const float*)d_in[4];
    const float* w_gate   = (const float*)d_in[5];
    const float* b_gate   = (const float*)d_in[6];
    const float* w_c_proj = (const float*)d_in[7];
    const float* b_c_proj = (const float*)d_in[8];
    float* out = (float*)d_out;

    const int W4 = (int)(WSZ / 4);
    wsplit2_kernel<<<2 * W4 / 256, 256>>>(w_c_fc, w_gate);            // 1
    router_kernel<<<NB * NT / 8, 256>>>(x, w_router, b_router);       // 2
    pos_kernel<<<1, 256>>>();                                         // 3 (includes src init)
    mlp1_kernel<<<dim3(NM / 128, NH / 64, NE), 256>>>(x, b_c_fc, b_gate);   // 4 <- ncu slot
    mlp2_kernel<<<dim3(NC / 128, NM / 128, NE), 256>>>(w_c_proj, b_c_proj); // 5
    combine_kernel<<<NB * NT, 192>>>(out);                            // 6
}

// round 15
// speedup vs baseline: 1.1469x; 1.1469x over previous
#include <cuda_runtime.h>
#include <cuda_bf16.h>
#include <math.h>
#include <stdint.h>

// ---------------------------------------------------------------- dims
#define NB   8
#define NT   2048
#define NC   768
#define NE   8
#define NKT  2
#define NH   3072
#define NCAP 640
#define NM   (NB * NCAP)   // 5120 rows per expert
#define WSZ  ((size_t)NE * NC * NH)   // elements per weight tensor

// ---------------------------------------------------------------- helpers
__device__ __forceinline__ uint32_t smem_u32(const void* p) {
    uint32_t a;
    asm("{ .reg .u64 t; cvta.to.shared.u64 t, %1; cvt.u32.u64 %0, t; }"
        : "=r"(a) : "l"(p));
    return a;
}
__device__ __forceinline__ void ldsm4(uint32_t* r, uint32_t a) {
    asm volatile("ldmatrix.sync.aligned.m8n8.x4.shared.b16 {%0,%1,%2,%3}, [%4];"
        : "=r"(r[0]), "=r"(r[1]), "=r"(r[2]), "=r"(r[3]) : "r"(a));
}
__device__ __forceinline__ void ldsm4t(uint32_t* r, uint32_t a) {
    asm volatile("ldmatrix.sync.aligned.m8n8.x4.trans.shared.b16 {%0,%1,%2,%3}, [%4];"
        : "=r"(r[0]), "=r"(r[1]), "=r"(r[2]), "=r"(r[3]) : "r"(a));
}
__device__ __forceinline__ void mma_bf16(float* d, const uint32_t* a, const uint32_t* b) {
    asm volatile(
        "mma.sync.aligned.m16n8k16.row.col.f32.bf16.bf16.f32 "
        "{%0,%1,%2,%3}, {%4,%5,%6,%7}, {%8,%9}, {%0,%1,%2,%3};"
        : "+f"(d[0]), "+f"(d[1]), "+f"(d[2]), "+f"(d[3])
        : "r"(a[0]), "r"(a[1]), "r"(a[2]), "r"(a[3]), "r"(b[0]), "r"(b[1]));
}
// tf32 mma m16n8k8
__device__ __forceinline__ void mma_tf32(float* d, const uint32_t* a, const uint32_t* b) {
    asm volatile(
        "mma.sync.aligned.m16n8k8.row.col.f32.tf32.tf32.f32 "
        "{%0,%1,%2,%3}, {%4,%5,%6,%7}, {%8,%9}, {%0,%1,%2,%3};"
        : "+f"(d[0]), "+f"(d[1]), "+f"(d[2]), "+f"(d[3])
        : "r"(a[0]), "r"(a[1]), "r"(a[2]), "r"(a[3]), "r"(b[0]), "r"(b[1]));
}
__device__ __forceinline__ uint32_t f2tf(uint32_t bits) {
    uint32_t o;
    asm("cvt.rna.tf32.f32 %0, %1;" : "=r"(o) : "f"(__uint_as_float(bits)));
    return o;
}
__device__ __forceinline__ float f2tf_f(float f) {
    uint32_t o;
    asm("cvt.rna.tf32.f32 %0, %1;" : "=r"(o) : "f"(f));
    return __uint_as_float(o);
}
// split float4 into packed bf16 hi (uint2) and lo residual (uint2)
__device__ __forceinline__ void split4(float4 v, uint2& h, uint2& l) {
    __nv_bfloat16 h0 = __float2bfloat16(v.x), h1 = __float2bfloat16(v.y);
    __nv_bfloat16 h2 = __float2bfloat16(v.z), h3 = __float2bfloat16(v.w);
    float r0 = v.x - __bfloat162float(h0), r1 = v.y - __bfloat162float(h1);
    float r2 = v.z - __bfloat162float(h2), r3 = v.w - __bfloat162float(h3);
    h.x = (uint32_t)__bfloat16_as_ushort(h0) | ((uint32_t)__bfloat16_as_ushort(h1) << 16);
    h.y = (uint32_t)__bfloat16_as_ushort(h2) | ((uint32_t)__bfloat16_as_ushort(h3) << 16);
    l.x = (uint32_t)__bfloat16_as_ushort(__float2bfloat16(r0))
        | ((uint32_t)__bfloat16_as_ushort(__float2bfloat16(r1)) << 16);
    l.y = (uint32_t)__bfloat16_as_ushort(__float2bfloat16(r2))
        | ((uint32_t)__bfloat16_as_ushort(__float2bfloat16(r3)) << 16);
}
#define CPA16(dst, src) \
    asm volatile("cp.async.cg.shared.global [%0], [%1], 16;" \
                 :: "r"((uint32_t)(dst)), "l"(src) : "memory")
#define CPA16Z(dst, src, sz) \
    asm volatile("cp.async.cg.shared.global [%0], [%1], 16, %2;" \
                 :: "r"((uint32_t)(dst)), "l"(src), "r"((uint32_t)(sz)) : "memory")
#define CP_COMMIT()  asm volatile("cp.async.commit_group;" ::: "memory")
#define CP_WAIT0()   asm volatile("cp.async.wait_group 0;"  ::: "memory")

// ---------------------------------------------------------------- scratch (≈654MB total)
__device__ __nv_bfloat16 g_acth[(size_t)NE * NM * NH];  // activation hi (252MB)
__device__ __nv_bfloat16 g_actl[(size_t)NE * NM * NH];  // activation lo (252MB)
// union buffer (151MB): phase 1 = transposed tf32 fc/gate weights, phase 2 = g_o.
__device__ __align__(1024) unsigned char g_u[8 * WSZ];
__device__ float g_p  [NB * NT * NKT];
__device__ int   g_ei [NB * NT * NKT];
__device__ int   g_pos[NB * NT * NKT];
__device__ int   g_src[NE * NM];

// ---------------------------------------------------------------- prep: transpose + tf32-round weights
// in [E][C][H] fp32 -> out [tensor][E][H][C] tf32-rounded fp32
__global__ void wtrans_kernel(const float* __restrict__ wfc,
                              const float* __restrict__ wgt) {
    __shared__ float t[32][33];
    float* gu = (float*)g_u;
    int z = blockIdx.z;
    int e = z >> 1, which = z & 1;
    const float* src = (which ? wgt : wfc) + (size_t)e * NC * NH;
    float* dst = gu + (size_t)which * NE * NH * NC + (size_t)e * NH * NC;
    int s0 = blockIdx.x * 32;   // H
    int r0 = blockIdx.y * 32;   // C
    int x = threadIdx.x, y = threadIdx.y;   // 32 x 8
    #pragma unroll
    for (int k = 0; k < 32; k += 8)
        t[y + k][x] = src[(size_t)(r0 + y + k) * NH + s0 + x];
    __syncthreads();
    #pragma unroll
    for (int k = 0; k < 32; k += 8)
        dst[(size_t)(s0 + y + k) * NC + r0 + x] = f2tf_f(t[x][y + k]);
}

// ---------------------------------------------------------------- router (unchanged, passing)
__global__ void router_kernel(const float* __restrict__ x,
                              const float* __restrict__ wr,
                              const float* __restrict__ br) {
    __shared__ float ws[NC * NE];
    int tid = threadIdx.x;
    const float4* wr4 = (const float4*)wr;
    float4* ws4 = (float4*)ws;
    #pragma unroll
    for (int i = tid; i < NC * NE / 4; i += 256) ws4[i] = wr4[i];
    __syncthreads();

    int warp = tid >> 5, lane = tid & 31;
    int token = blockIdx.x * 8 + warp;
    const float* xrow = x + (size_t)token * NC;

    float acc[NE];
    #pragma unroll
    for (int e = 0; e < NE; e++) acc[e] = 0.f;
    for (int c = lane; c < NC; c += 32) {
        float xv = xrow[c];
        #pragma unroll
        for (int e = 0; e < NE; e++) acc[e] = fmaf(xv, ws[c * NE + e], acc[e]);
    }
    #pragma unroll
    for (int e = 0; e < NE; e++) {
        #pragma unroll
        for (int off = 16; off; off >>= 1)
            acc[e] += __shfl_xor_sync(0xffffffffu, acc[e], off);
    }
    if (lane == 0) {
        float l[NE], p[NE];
        float mx = -1e30f;
        #pragma unroll
        for (int e = 0; e < NE; e++) { l[e] = acc[e] + br[e]; mx = fmaxf(mx, l[e]); }
        float s = 0.f;
        #pragma unroll
        for (int e = 0; e < NE; e++) { p[e] = expf(l[e] - mx); s += p[e]; }
        float inv = 1.f / s;
        #pragma unroll
        for (int e = 0; e < NE; e++) p[e] *= inv;

        int i1 = 0; float p1 = p[0];
        #pragma unroll
        for (int e = 1; e < NE; e++) if (p[e] > p1) { p1 = p[e]; i1 = e; }
        int i2 = -1; float p2 = -1.f;
        #pragma unroll
        for (int e = 0; e < NE; e++) if (e != i1 && p[e] > p2) { p2 = p[e]; i2 = e; }

        g_p [token * 2 + 0] = p1;  g_p [token * 2 + 1] = p2;
        g_ei[token * 2 + 0] = i1;  g_ei[token * 2 + 1] = i2;
    }
}

// capacity scan (absorbs fill_src; exact k-major cumsum order per batch)
__global__ void pos_kernel() {
    __shared__ int cnt[8][NE];
    for (int i = threadIdx.x; i < NE * NM; i += 256) g_src[i] = -1;
    int w = threadIdx.x >> 5, lane = threadIdx.x & 31;
    int b = w;
    if (lane < NE) cnt[w][lane] = 0;
    __syncthreads();
    for (int k = 0; k < NKT; k++) {
        for (int t0 = 0; t0 < NT; t0 += 32) {
            int t = t0 + lane;
            int e = g_ei[(b * NT + t) * NKT + k];
            unsigned mask = __match_any_sync(0xffffffffu, e);
            int prefix = __popc(mask & ((1u << lane) - 1u));
            int base = cnt[w][e];
            __syncwarp();
            int pos = base + prefix;
            g_pos[(b * NT + t) * NKT + k] = pos;
            if (pos < NCAP) g_src[e * NM + b * NCAP + pos] = b * NT + t;
            if (lane == (31 - __clz(mask))) cnt[w][e] = base + __popc(mask);
            __syncwarp();
        }
    }
}

// ---------------------------------------------------------------- mlp1 (1xTF32; all-cp.async fill)
// stage: A [128 rows x 80B] = 10240, B [128 n-rows x 80B] = 10240 (rows 0-63 fc, 64-127 gate)
#define STG1  20480
#define M1_A  0
#define M1_B  10240

__global__ void __launch_bounds__(256) mlp1_kernel(const float* __restrict__ x,
                                                   const float* __restrict__ bfc,
                                                   const float* __restrict__ bgt) {
    __shared__ __align__(16) unsigned char SM[2 * STG1];   // 40960 B
    __shared__ int s_src[128];
    const uint32_t sb = smem_u32(SM);
    const int tid = threadIdx.x;
    const int e = blockIdx.z;
    const int m0 = blockIdx.x * 128, n0 = blockIdx.y * 64;   // m fastest (weights dedup in L2)

    if (tid < 128) s_src[tid] = g_src[e * NM + m0 + tid];
    __syncthreads();   // s_src MUST be visible before the first gather read

    const float* WTf = (const float*)g_u + (size_t)e * NH * NC;
    const float* WTg = (const float*)g_u + (size_t)NE * NH * NC + (size_t)e * NH * NC;

    const int wid = tid >> 5, lane = tid & 31;
    const int mwarp = wid >> 1, nwarp = wid & 1;
    // A ldsm pointer (b16-view of fp32): rows = lane&15, chunk sel by lane&16
    const uint32_t a_off = (uint32_t)(mwarp * 32 + (lane & 15)) * 80 + ((lane & 16) ? 16 : 0);
    // B ldsm pointer: 8 n-rows, 4 k-chunks of 16B
    const uint32_t b_off = (uint32_t)(lane & 7) * 80 + (uint32_t)((lane >> 3) & 3) * 16;

    float acch[2][4][4] = {};
    float accg[2][4][4] = {};

    auto cpAB = [&](int s, int buf) {
        const int k0 = s * 16;
        const uint32_t base = sb + buf * STG1;
        // A: 128 rows x 4 chunks, 2/thread (zfill for empty slots)
        #pragma unroll
        for (int i = 0; i < 2; i++) {
            int j = tid + i * 256;
            int r = j >> 2, ch = j & 3;
            int srow = s_src[r];
            const float* src = x + (size_t)(srow >= 0 ? srow : 0) * NC + k0 + ch * 4;
            CPA16Z(base + M1_A + (uint32_t)r * 80 + ch * 16, src, (srow >= 0) ? 16 : 0);
        }
        // B: 128 n-rows (fc 0-63, gate 64-127) x 4 chunks, 2/thread
        #pragma unroll
        for (int i = 0; i < 2; i++) {
            int j = tid + i * 256;
            int r = j >> 2, ch = j & 3;
            const float* w = (r < 64) ? (WTf + (size_t)(n0 + r) * NC)
                                      : (WTg + (size_t)(n0 + r - 64) * NC);
            CPA16(base + M1_B + (uint32_t)r * 80 + ch * 16, w + k0 + ch * 4);
        }
    };

    cpAB(0, 0);
    CP_COMMIT();

    const int NS = NC / 16;   // 48
    for (int s = 0; s < NS; s++) {
        const int buf = s & 1;
        CP_WAIT0();
        __syncthreads();
        if (s + 1 < NS) {
            cpAB(s + 1, buf ^ 1);
            CP_COMMIT();
        }
        const uint32_t base = sb + buf * STG1;

        // A fragments: [16m x 16k fp32] per (mt, k8-step); cvt.rna to tf32
        uint32_t af[2][8];
        #pragma unroll
        for (int mt = 0; mt < 2; mt++) {
            ldsm4(&af[mt][0], base + M1_A + a_off + mt * 1280);        // k 0-7
            ldsm4(&af[mt][4], base + M1_A + a_off + mt * 1280 + 32);   // k 8-15
            #pragma unroll
            for (int q = 0; q < 8; q++) af[mt][q] = f2tf(af[mt][q]);
        }

        #pragma unroll
        for (int nt = 0; nt < 4; nt++) {
            uint32_t bfr[4], bgr[4];
            uint32_t nrow = (uint32_t)(nwarp * 32 + nt * 8) * 80;
            ldsm4(bfr, base + M1_B + nrow + b_off);             // fc
            ldsm4(bgr, base + M1_B + nrow + 64 * 80 + b_off);   // gate
            #pragma unroll
            for (int mt = 0; mt < 2; mt++) {
                mma_tf32(acch[mt][nt], &af[mt][0], &bfr[0]);
                mma_tf32(acch[mt][nt], &af[mt][4], &bfr[2]);
                mma_tf32(accg[mt][nt], &af[mt][0], &bgr[0]);
                mma_tf32(accg[mt][nt], &af[mt][4], &bgr[2]);
            }
        }
    }

    // epilogue: silu(h*g) -> bf16 hi/lo activations (unchanged)
    const int qr = lane >> 2, qc = (lane & 3) * 2;
    #pragma unroll
    for (int mt = 0; mt < 2; mt++) {
        #pragma unroll
        for (int nt = 0; nt < 4; nt++) {
            const int col = n0 + nwarp * 32 + nt * 8 + qc;
            const float b0 = bfc[e * NH + col], b1 = bfc[e * NH + col + 1];
            const float c0 = bgt[e * NH + col], c1 = bgt[e * NH + col + 1];
            #pragma unroll
            for (int hf = 0; hf < 2; hf++) {
                const int row = m0 + mwarp * 32 + mt * 16 + qr + hf * 8;
                float h0 = acch[mt][nt][hf * 2 + 0] + b0;
                float h1 = acch[mt][nt][hf * 2 + 1] + b1;
                float g0 = accg[mt][nt][hf * 2 + 0] + c0;
                float g1 = accg[mt][nt][hf * 2 + 1] + c1;
                float z0 = h0 * g0, z1 = h1 * g1;
                float v0 = z0 / (1.f + expf(-z0));
                float v1 = z1 / (1.f + expf(-z1));
                __nv_bfloat16 H0 = __float2bfloat16(v0), H1 = __float2bfloat16(v1);
                float r0 = v0 - __bfloat162float(H0);
                float r1 = v1 - __bfloat162float(H1);
                uint32_t hi = (uint32_t)__bfloat16_as_ushort(H0)
                            | ((uint32_t)__bfloat16_as_ushort(H1) << 16);
                uint32_t lo = (uint32_t)__bfloat16_as_ushort(__float2bfloat16(r0))
                            | ((uint32_t)__bfloat16_as_ushort(__float2bfloat16(r1)) << 16);
                size_t off = ((size_t)(e * NM + row)) * NH + col;
                *(uint32_t*)(g_acth + off) = hi;
                *(uint32_t*)(g_actl + off) = lo;
            }
        }
    }
}

// ---------------------------------------------------------------- mlp2 (HMMA hi/lo, CTA 128x128, reg-prefetch) — R12 proven
#define STG2  20992
#define M2_AH 0
#define M2_AL 6144
#define M2_BH 12288
#define M2_BL 16640

__global__ void __launch_bounds__(256) mlp2_kernel(const float* __restrict__ wp,
                                                   const float* __restrict__ bp) {
    __shared__ __align__(16) unsigned char SM[2 * STG2];   // 41984 B
    const uint32_t sb = smem_u32(SM);
    const int tid = threadIdx.x;
    const int e = blockIdx.z;
    const int n0 = blockIdx.x * 128, m0 = blockIdx.y * 128;

    const __nv_bfloat16* Ah = g_acth + ((size_t)e * NM + m0) * NH;
    const __nv_bfloat16* Al = g_actl + ((size_t)e * NM + m0) * NH;
    const float* W = wp + (size_t)e * NH * NC;
    float* g_o = (float*)g_u;                    // reuse union buffer

    const int wid = tid >> 5, lane = tid & 31;
    const int mwarp = wid >> 1, nwarp = wid & 1;
    const uint32_t a_off = (uint32_t)(mwarp * 32 + (lane & 15)) * 48 + ((lane & 16) ? 16 : 0);
    const uint32_t bt_off = (uint32_t)(lane & 15) * 272 + ((lane & 16) ? 16 : 0) + nwarp * 128;

    float acc[2][8][4] = {};

    uint2 pAh[2], pAl[2];
    float4 pB[2];

    auto ld_stage = [&](int s) {
        const int k0 = s * 16;
        #pragma unroll
        for (int i = 0; i < 2; i++) {
            int j = tid + i * 256;
            int r = j >> 2, ch = j & 3;
            size_t goff = (size_t)r * NH + k0 + ch * 4;
            pAh[i] = *(const uint2*)(Ah + goff);
            pAl[i] = *(const uint2*)(Al + goff);
        }
        #pragma unroll
        for (int i = 0; i < 2; i++) {
            int j = tid + i * 256;
            int r = j >> 5, ch = j & 31;
            pB[i] = *(const float4*)(W + (size_t)(k0 + r) * NC + n0 + ch * 4);
        }
    };
    auto st_stage = [&](int buf) {
        const uint32_t base = buf * STG2;
        #pragma unroll
        for (int i = 0; i < 2; i++) {
            int j = tid + i * 256;
            int r = j >> 2, ch = j & 3;
            uint32_t d = base + (uint32_t)r * 48 + ch * 8;
            *(uint2*)(SM + M2_AH + d) = pAh[i];
            *(uint2*)(SM + M2_AL + d) = pAl[i];
        }
        #pragma unroll
        for (int i = 0; i < 2; i++) {
            int j = tid + i * 256;
            int r = j >> 5, ch = j & 31;
            uint2 h, l;
            split4(pB[i], h, l);
            uint32_t d = base + (uint32_t)r * 272 + ch * 8;
            *(uint2*)(SM + M2_BH + d) = h;
            *(uint2*)(SM + M2_BL + d) = l;
        }
    };

    const int NS = NH / 16;   // 192
    ld_stage(0);
    for (int s = 0; s < NS; s++) {
        const int buf = s & 1;
        st_stage(buf);
        __syncthreads();
        if (s + 1 < NS) ld_stage(s + 1);
        const uint32_t base = sb + buf * STG2;

        uint32_t ah[2][4], al[2][4];
        #pragma unroll
        for (int mt = 0; mt < 2; mt++) {
            ldsm4(ah[mt], base + M2_AH + a_off + mt * 768);
            ldsm4(al[mt], base + M2_AL + a_off + mt * 768);
        }
        uint32_t bh[4][4], bl[4][4];
        #pragma unroll
        for (int q = 0; q < 4; q++) {
            uint32_t bo = bt_off + q * 32;
            ldsm4t(bh[q], base + M2_BH + bo);
            ldsm4t(bl[q], base + M2_BL + bo);
        }
        #pragma unroll
        for (int mt = 0; mt < 2; mt++)
            #pragma unroll
            for (int nt = 0; nt < 8; nt++) {
                const uint32_t* BH = &bh[nt >> 1][(nt & 1) * 2];
                const uint32_t* BL = &bl[nt >> 1][(nt & 1) * 2];
                mma_bf16(acc[mt][nt], ah[mt], BH);
                mma_bf16(acc[mt][nt], al[mt], BH);
                mma_bf16(acc[mt][nt], ah[mt], BL);
            }
    }

    const int qr = lane >> 2, qc = (lane & 3) * 2;
    #pragma unroll
    for (int mt = 0; mt < 2; mt++) {
        #pragma unroll
        for (int nt = 0; nt < 8; nt++) {
            const int col = n0 + nwarp * 64 + nt * 8 + qc;
            const float b0 = bp[e * NC + col], b1 = bp[e * NC + col + 1];
            #pragma unroll
            for (int hf = 0; hf < 2; hf++) {
                const int row = m0 + mwarp * 32 + mt * 16 + qr + hf * 8;
                float2 o;
                o.x = acc[mt][nt][hf * 2 + 0] + b0;
                o.y = acc[mt][nt][hf * 2 + 1] + b1;
                *(float2*)(g_o + ((size_t)(e * NM + row)) * NC + col) = o;
            }
        }
    }
}

// ---------------------------------------------------------------- combine (reads g_o from union)
__global__ void combine_kernel(float* __restrict__ out) {
    const float* g_o = (const float*)g_u;
    int token = blockIdx.x;
    int b = token / NT;

    int e0 = g_ei[token * 2 + 0], e1 = g_ei[token * 2 + 1];
    float p0 = g_p[token * 2 + 0], p1 = g_p[token * 2 + 1];
    int q0 = min(g_pos[token * 2 + 0], NCAP - 1);
    int q1 = min(g_pos[token * 2 + 1], NCAP - 1);

    const float4* r0 = (const float4*)(g_o + ((size_t)e0 * NM + b * NCAP + q0) * NC);
    const float4* r1 = (const float4*)(g_o + ((size_t)e1 * NM + b * NCAP + q1) * NC);

    int c = threadIdx.x;
    float4 v0 = r0[c], v1 = r1[c];
    float4 o;
    o.x = p0 * v0.x + p1 * v1.x;
    o.y = p0 * v0.y + p1 * v1.y;
    o.z = p0 * v0.z + p1 * v1.z;
    o.w = p0 * v0.w + p1 * v1.w;
    ((float4*)out)[(size_t)token * (NC / 4) + c] = o;
}

// ---------------------------------------------------------------- launch
extern "C" void kernel_launch(void* const* d_in, const int* in_sizes, int n_in,
                              void* d_out, int out_size) {
    const float* x        = (const float*)d_in[0];
    const float* w_router = (const float*)d_in[1];
    const float* b_router = (const float*)d_in[2];
    const float* w_c_fc   = (const float*)d_in[3];
    const float* b_c_fc   = (const float*)d_in[4];
    const float* w_gate   = (const float*)d_in[5];
    const float* b_gate   = (const float*)d_in[6];
    const float* w_c_proj = (const float*)d_in[7];
    const float* b_c_proj = (const float*)d_in[8];
    float* out = (float*)d_out;

    wtrans_kernel<<<dim3(NH / 32, NC / 32, NE * 2), dim3(32, 8)>>>(w_c_fc, w_gate);  // 1
    router_kernel<<<NB * NT / 8, 256>>>(x, w_router, b_router);                      // 2
    pos_kernel<<<1, 256>>>();                                                        // 3
    mlp1_kernel<<<dim3(NM / 128, NH / 64, NE), 256>>>(x, b_c_fc, b_gate);            // 4 <- ncu slot
    mlp2_kernel<<<dim3(NC / 128, NM / 128, NE), 256>>>(w_c_proj, b_c_proj);          // 5
    combine_kernel<<<NB * NT, 192>>>(out);                                           // 6
}